// round 13
// baseline (speedup 1.0000x reference)
#include <cuda_runtime.h>
#include <cuda_bf16.h>

#define B_ 128
#define H_ 512
#define HG_ 2048
#define T_ 512
#define FIN 64
#define FOUT 8
#define WOUT 64
#define NCTA 128
#define NTHR 512
#define NTOT (NCTA*NTHR)
#define DP 3
#define WSLOT 3072                       // 6 streams x 512B
#define RING_B (16*DP*WSLOT)             // 147456
#define SMEM_TOTAL (RING_B + 4*2304*4)   // +36KB sred = 184320

// W: [(ntile*NK16+k16)*32+lane] = {b0h,b1h,b0l,b1l}
// A: [((mtile*nk+k16)*32+lane)*2 + {0hi,1lo}]
__device__ __align__(16) uint4 gWp[6][524288];
__device__ __align__(16) uint4 gXp[1048576];
__device__ __align__(16) uint4 gPh[2][3][16384];
__device__ __align__(16) uint4 gPp[512];
__device__ float gBias[6][HG_];
__device__ float g_h[3][B_][H_];
__device__ float g_c[3][B_][H_];
__device__ unsigned g_cnt = 0;
__device__ volatile unsigned g_gen = 0;
__device__ unsigned g_cnt4[4*32];
__device__ volatile unsigned g_gen4[4*32];

__device__ __forceinline__ float sigmoidf_(float x){ return 1.f/(1.f+expf(-x)); }
__device__ __forceinline__ void bsplit(float v, unsigned short& h, unsigned short& l){
    __nv_bfloat16 bh = __float2bfloat16(v);
    __nv_bfloat16 bl = __float2bfloat16(v - __bfloat162float(bh));
    h = __bfloat16_as_ushort(bh); l = __bfloat16_as_ushort(bl);
}
__device__ __forceinline__ unsigned packu(unsigned short e, unsigned short o){
    return (unsigned)e | ((unsigned)o << 16);
}
__device__ __forceinline__ void grid_barrier(){
    __syncthreads();
    if (threadIdx.x == 0){
        __threadfence();
        unsigned gen = g_gen;
        if (atomicAdd(&g_cnt,1u) == NCTA-1){ g_cnt = 0; __threadfence(); g_gen = gen+1; }
        else { while (g_gen == gen) {} }
        __threadfence();
    }
    __syncthreads();
}
__device__ __forceinline__ void group_barrier(int grp){
    __syncthreads();
    if (threadIdx.x == 0){
        __threadfence();
        unsigned* cnt = &g_cnt4[grp*32];
        volatile unsigned* gen = &g_gen4[grp*32];
        unsigned gv = *gen;
        if (atomicAdd(cnt,1u) == 31){ *cnt = 0; __threadfence(); *gen = gv+1; }
        else { while (*gen == gv) {} }
        __threadfence();
    }
    __syncthreads();
}
__device__ __forceinline__ void cpasync16(void* s, const void* g){
    unsigned sa = (unsigned)__cvta_generic_to_shared(s);
    asm volatile("cp.async.cg.shared.global [%0], [%1], 16;" :: "r"(sa), "l"(g));
}
__device__ __forceinline__ void mma_bf16(float* d, const uint4 a, unsigned b0, unsigned b1){
    asm volatile("mma.sync.aligned.m16n8k16.row.col.f32.bf16.bf16.f32 "
        "{%0,%1,%2,%3}, {%4,%5,%6,%7}, {%8,%9}, {%0,%1,%2,%3};"
        : "+f"(d[0]), "+f"(d[1]), "+f"(d[2]), "+f"(d[3])
        : "r"(a.x), "r"(a.y), "r"(a.z), "r"(a.w), "r"(b0), "r"(b1));
}

// fused layer-step; warp-private cp.async ring (depth 3), no in-loop barriers.
// CTA tile 32b x 16j x 4 quadrants; 16 warps = 4 kg x (2 mw x 2 jh).
__device__ __noinline__ void layer_step(
    char* smem, int tid,
    const uint4* __restrict__ pA1, int nk1,
    const uint4* __restrict__ pA2,
    const uint4* __restrict__ pW, const float* __restrict__ bias,
    int l, uint4* __restrict__ pHw, int j0, int bt)
{
    const int wid = tid>>5, lane = tid&31;
    const int kg = wid>>2, sub = wid&3, mw = sub&1, jh = sub>>1;
    const int NK16 = nk1 + 32;
    const int mtile = bt*2 + mw;
    const int g = lane>>2, tig = lane&3;
    const int nb = (j0>>3) + jh;

    char* ring = smem + wid*(DP*WSLOT);
    float* sred = (float*)(smem + RING_B);

    const uint4* wp0 = pW + ((size_t)(0*64 + nb)*NK16 + kg)*32 + lane;
    const uint4* wp1 = pW + ((size_t)(1*64 + nb)*NK16 + kg)*32 + lane;
    const uint4* wp2 = pW + ((size_t)(2*64 + nb)*NK16 + kg)*32 + lane;
    const uint4* wp3 = pW + ((size_t)(3*64 + nb)*NK16 + kg)*32 + lane;

    auto aptr = [&](int i) -> const uint4* {
        return (i < nk1) ? pA1 + ((size_t)(mtile*nk1 + i)*32 + lane)*2
                         : pA2 + ((size_t)(mtile*32 + (i-nk1))*32 + lane)*2;
    };
    auto issue = [&](int r){
        int k16 = kg + 4*r;
        if (k16 < NK16){
            char* slot = ring + (r % DP)*WSLOT;
            cpasync16(slot + 0*512 + lane*16, wp0 + (size_t)r*128);
            cpasync16(slot + 1*512 + lane*16, wp1 + (size_t)r*128);
            cpasync16(slot + 2*512 + lane*16, wp2 + (size_t)r*128);
            cpasync16(slot + 3*512 + lane*16, wp3 + (size_t)r*128);
            const uint4* ap = aptr(k16);
            cpasync16(slot + 4*512 + lane*16, ap);
            cpasync16(slot + 5*512 + lane*16, ap + 1);
        }
        asm volatile("cp.async.commit_group;" ::: "memory");
    };

    float acc[4][4];
    #pragma unroll
    for (int q = 0; q < 4; q++){ acc[q][0]=acc[q][1]=acc[q][2]=acc[q][3]=0.f; }

    const int myN = (NK16 - kg + 3) >> 2;
    issue(0); issue(1);

    for (int r = 0; r < myN; r++){
        asm volatile("cp.async.wait_group 1;" ::: "memory");
        char* slot = ring + (r % DP)*WSLOT;
        uint4 w0  = *(const uint4*)(slot + 0*512 + lane*16);
        uint4 w1  = *(const uint4*)(slot + 1*512 + lane*16);
        uint4 w2  = *(const uint4*)(slot + 2*512 + lane*16);
        uint4 w3  = *(const uint4*)(slot + 3*512 + lane*16);
        uint4 ahi = *(const uint4*)(slot + 4*512 + lane*16);
        uint4 alo = *(const uint4*)(slot + 5*512 + lane*16);
        issue(r + 2);
        mma_bf16(acc[0], ahi, w0.x, w0.y);
        mma_bf16(acc[1], ahi, w1.x, w1.y);
        mma_bf16(acc[2], ahi, w2.x, w2.y);
        mma_bf16(acc[3], ahi, w3.x, w3.y);
        mma_bf16(acc[0], ahi, w0.z, w0.w);
        mma_bf16(acc[1], ahi, w1.z, w1.w);
        mma_bf16(acc[2], ahi, w2.z, w2.w);
        mma_bf16(acc[3], ahi, w3.z, w3.w);
        mma_bf16(acc[0], alo, w0.x, w0.y);
        mma_bf16(acc[1], alo, w1.x, w1.y);
        mma_bf16(acc[2], alo, w2.x, w2.y);
        mma_bf16(acc[3], alo, w3.x, w3.y);
    }

    __syncthreads();
    {
        float* rg = sred + kg*2304;
        #pragma unroll
        for (int q = 0; q < 4; q++){
            float* t0 = rg + (q*16 + jh*8 + 2*tig)*36 + mw*16;
            t0[g] = acc[q][0]; t0[g+8] = acc[q][2];
            t0[36+g] = acc[q][1]; t0[36+g+8] = acc[q][3];
        }
    }
    __syncthreads();

    {   // cell phase: thread -> (b_l = tid>>4, j_l = tid&15)
        const int b_l = tid>>4, j_l = tid&15;
        float gate[4];
        #pragma unroll
        for (int q = 0; q < 4; q++){
            float s = 0.f;
            #pragma unroll
            for (int kk = 0; kk < 4; kk++) s += sred[kk*2304 + (q*16+j_l)*36 + b_l];
            gate[q] = s + bias[q*H_ + j0 + j_l];
        }
        const int b = bt*32 + b_l, j = j0 + j_l;
        float co = g_c[l][b][j];
        float cn = sigmoidf_(gate[1])*co + sigmoidf_(gate[0])*tanhf(gate[2]);
        g_c[l][b][j] = cn;
        float hv = sigmoidf_(gate[3])*tanhf(cn);
        g_h[l][b][j] = hv;
        unsigned short hs, ls; bsplit(hv, hs, ls);
        int mt = b>>4, rb = b&15, gg = rb&7, a01 = rb>>3;
        int k16 = j>>4, kr = j&15, tg = (kr>>1)&3, r24 = kr>>3, half = kr&1;
        int regidx = a01 + (r24<<1);
        unsigned short* dst = (unsigned short*)
            (pHw + ((size_t)(mt*32 + k16)*32 + (gg*4 + tg))*2);
        dst[regidx*2 + half] = hs;
        dst[8 + regidx*2 + half] = ls;
    }
}

__global__ __launch_bounds__(NTHR, 1) void lstm_persist(
    const float* __restrict__ x,
    const float* __restrict__ eWih0, const float* __restrict__ eWih,
    const float* __restrict__ eWhh,  const float* __restrict__ ebih,
    const float* __restrict__ ebhh,
    const float* __restrict__ dWih0, const float* __restrict__ dWih,
    const float* __restrict__ dWhh,  const float* __restrict__ dbih,
    const float* __restrict__ dbhh,
    const float* __restrict__ fcw,   const float* __restrict__ fcb,
    float* __restrict__ out)
{
    extern __shared__ char smem[];
    const int tid = threadIdx.x;
    const int bt = blockIdx.x >> 5;
    const int j0 = (blockIdx.x & 31)*16;
    const int grp = bt;
    const int gid = blockIdx.x*NTHR + tid;
    const size_t WS = (size_t)HG_*H_;

    // ---------------- init + packing ----------------
    for (int i = gid; i < 3*B_*H_; i += NTOT) (&g_c[0][0][0])[i] = 0.f;
    for (int i = gid; i < 2*3*16384; i += NTOT) (&gPh[0][0][0])[i] = make_uint4(0,0,0,0);
    {
        const float* bis[6] = {ebih, ebih+HG_, ebih+2*HG_, dbih, dbih+HG_, dbih+2*HG_};
        const float* bhs[6] = {ebhh, ebhh+HG_, ebhh+2*HG_, dbhh, dbhh+HG_, dbhh+2*HG_};
        for (int i = gid; i < 6*HG_; i += NTOT){
            int s = i >> 11, n = i & (HG_-1);
            gBias[s][n] = bis[s][n] + bhs[s][n];
        }
    }
    if (gid < 256){   // seed decoder input x[:, FIN-1, 0:FOUT]
        int mt = gid>>5, lane = gid&31, g = lane>>2, tig = lane&3;
        unsigned short hv[8], lv[8];
        #pragma unroll
        for (int ri = 0; ri < 4; ri++){
            int r24 = ri>>1, a01 = ri&1;
            #pragma unroll
            for (int half = 0; half < 2; half++){
                int k = r24*8 + 2*tig + half;
                int b = mt*16 + a01*8 + g;
                float v = (k < FOUT) ? x[(size_t)b*(FIN*T_) + (size_t)(FIN-1)*T_ + k] : 0.f;
                bsplit(v, hv[ri*2+half], lv[ri*2+half]);
            }
        }
        gPp[(size_t)(mt*32+lane)*2]   = make_uint4(packu(hv[0],hv[1]),packu(hv[2],hv[3]),packu(hv[4],hv[5]),packu(hv[6],hv[7]));
        gPp[(size_t)(mt*32+lane)*2+1] = make_uint4(packu(lv[0],lv[1]),packu(lv[2],lv[3]),packu(lv[4],lv[5]),packu(lv[6],lv[7]));
    }
    for (int idx = gid; idx < T_*8*4*32; idx += NTOT){   // pack x
        int lane = idx&31, k16 = (idx>>5)&3, mt = (idx>>7)&7, t = idx>>10;
        int g = lane>>2, tig = lane&3;
        int r0 = mt*16 + g, k0 = k16*16 + 2*tig;
        const float* xa = x + (size_t)r0*(FIN*T_) + t;
        const float* xb = x + (size_t)(r0+8)*(FIN*T_) + t;
        unsigned short h[8], l[8];
        bsplit(xa[(size_t)(k0  )*T_], h[0], l[0]); bsplit(xa[(size_t)(k0+1)*T_], h[1], l[1]);
        bsplit(xb[(size_t)(k0  )*T_], h[2], l[2]); bsplit(xb[(size_t)(k0+1)*T_], h[3], l[3]);
        bsplit(xa[(size_t)(k0+8)*T_], h[4], l[4]); bsplit(xa[(size_t)(k0+9)*T_], h[5], l[5]);
        bsplit(xb[(size_t)(k0+8)*T_], h[6], l[6]); bsplit(xb[(size_t)(k0+9)*T_], h[7], l[7]);
        gXp[(size_t)idx*2]   = make_uint4(packu(h[0],h[1]),packu(h[2],h[3]),packu(h[4],h[5]),packu(h[6],h[7]));
        gXp[(size_t)idx*2+1] = make_uint4(packu(l[0],l[1]),packu(l[2],l[3]),packu(l[4],l[5]),packu(l[6],l[7]));
    }
    {   // pack weights
        const float* W1s[6] = {eWih0, eWih, eWih+WS, dWih0, dWih, dWih+WS};
        const float* W2s[6] = {eWhh, eWhh+WS, eWhh+2*WS, dWhh, dWhh+WS, dWhh+2*WS};
        const int K1s[6] = {64,512,512,8,512,512};
        const int nk1s[6] = {4,32,32,1,32,32};
        for (int s = 0; s < 6; s++){
            const float* W1 = W1s[s]; const float* W2 = W2s[s];
            const int K1 = K1s[s], NK16 = nk1s[s]+32, nk1 = nk1s[s];
            for (int idx = gid; idx < 256*NK16*32; idx += NTOT){
                int lane = idx&31, k16 = (idx>>5)%NK16, ntile = (idx>>5)/NK16;
                int g = lane>>2, tig = lane&3;
                int n = ntile*8 + g, kb = k16*16 + 2*tig;
                float v00,v01,v10,v11;
                if (k16 < nk1){
                    v00 = (kb  <K1)? W1[(size_t)n*K1+kb]  :0.f;
                    v01 = (kb+1<K1)? W1[(size_t)n*K1+kb+1]:0.f;
                    v10 = (kb+8<K1)? W1[(size_t)n*K1+kb+8]:0.f;
                    v11 = (kb+9<K1)? W1[(size_t)n*K1+kb+9]:0.f;
                } else {
                    int k2 = kb - nk1*16;
                    v00 = W2[(size_t)n*H_+k2];   v01 = W2[(size_t)n*H_+k2+1];
                    v10 = W2[(size_t)n*H_+k2+8]; v11 = W2[(size_t)n*H_+k2+9];
                }
                unsigned short h00,l00,h01,l01,h10,l10,h11,l11;
                bsplit(v00,h00,l00); bsplit(v01,h01,l01);
                bsplit(v10,h10,l10); bsplit(v11,h11,l11);
                gWp[s][idx] = make_uint4(packu(h00,h01),packu(h10,h11),packu(l00,l01),packu(l10,l11));
            }
        }
    }
    grid_barrier();

    // -------- encoder: layer wavefront, 1 group barrier / super-step --------
    int rp0 = 0, rp1 = 0, rp2 = 0;
    for (int s = 0; s < T_ + 2; ++s){
        int r0 = rp0, r1 = rp1, r2 = rp2;
        if (s < T_){
            layer_step(smem, tid, gXp+(size_t)s*2048, 4, &gPh[r0][0][0],
                       gWp[0], gBias[0], 0, &gPh[r0^1][0][0], j0, bt);
            rp0 ^= 1;
        }
        if (s >= 1 && s < T_ + 1){
            layer_step(smem, tid, &gPh[r0][0][0], 32, &gPh[r1][1][0],
                       gWp[1], gBias[1], 1, &gPh[r1^1][1][0], j0, bt);
            rp1 ^= 1;
        }
        if (s >= 2){
            layer_step(smem, tid, &gPh[r1][1][0], 32, &gPh[r2][2][0],
                       gWp[2], gBias[2], 2, &gPh[r2^1][2][0], j0, bt);
            rp2 ^= 1;
        }
        group_barrier(grp);
    }

    // -------- decoder: serial 4-phase loop --------
    for (int d = 0; d < WOUT; ++d){
        layer_step(smem, tid, gPp, 1, &gPh[rp0][0][0],
                   gWp[3], gBias[3], 0, &gPh[rp0^1][0][0], j0, bt);
        rp0 ^= 1; group_barrier(grp);
        layer_step(smem, tid, &gPh[rp0][0][0], 32, &gPh[rp1][1][0],
                   gWp[4], gBias[4], 1, &gPh[rp1^1][1][0], j0, bt);
        rp1 ^= 1; group_barrier(grp);
        layer_step(smem, tid, &gPh[rp1][1][0], 32, &gPh[rp2][2][0],
                   gWp[5], gBias[5], 2, &gPh[rp2^1][2][0], j0, bt);
        rp2 ^= 1; group_barrier(grp);
        if (tid < 256){   // FC head: CTA = batch row b
            int f = tid>>5, lnn = tid&31, b = blockIdx.x;
            const float* hrow = &g_h[2][b][0];
            const float* wrow = fcw + f*H_;
            float ssum = 0.f;
            #pragma unroll 4
            for (int j = lnn; j < H_; j += 32) ssum += hrow[j]*wrow[j];
            #pragma unroll
            for (int o = 16; o; o >>= 1) ssum += __shfl_down_sync(0xffffffffu, ssum, o);
            if (lnn == 0){
                float v = ssum + fcb[f];
                out[(size_t)b*(FOUT*WOUT) + f*WOUT + d] = v;
                unsigned short hs, ls; bsplit(v, hs, ls);
                int mt = b>>4, gg = b&7, a01 = (b>>3)&1;
                int tg = (f>>1)&3, half = f&1;
                unsigned short* dst = (unsigned short*)
                    (gPp + ((size_t)mt*32 + (gg*4 + tg))*2);
                dst[a01*2 + half] = hs;
                dst[8 + a01*2 + half] = ls;
            }
        }
        group_barrier(grp);
    }
}

extern "C" void kernel_launch(void* const* d_in, const int* in_sizes, int n_in,
                              void* d_out, int out_size)
{
    cudaFuncSetAttribute(lstm_persist,
                         cudaFuncAttributeMaxDynamicSharedMemorySize, SMEM_TOTAL);
    lstm_persist<<<NCTA, NTHR, SMEM_TOTAL>>>(
        (const float*)d_in[0], (const float*)d_in[1], (const float*)d_in[2],
        (const float*)d_in[3], (const float*)d_in[4], (const float*)d_in[5],
        (const float*)d_in[6], (const float*)d_in[7], (const float*)d_in[8],
        (const float*)d_in[9], (const float*)d_in[10], (const float*)d_in[11],
        (const float*)d_in[12], (float*)d_out);
}

// round 14
// speedup vs baseline: 1.7184x; 1.7184x over previous
#include <cuda_runtime.h>
#include <cuda_bf16.h>

#define B_ 128
#define H_ 512
#define HG_ 2048
#define T_ 512
#define FIN 64
#define FOUT 8
#define WOUT 64
#define NCTA 256
#define NTHR 256
#define NTOT (NCTA*NTHR)

// W: [(ntile*NK16+k16)*32+lane] = {b0h,b1h,b0l,b1l}
// A: [((mtile*nk+k16)*32+lane)*2 + {0hi,1lo}]
__device__ __align__(16) uint4 gWp[6][524288];
__device__ __align__(16) uint4 gXp[1048576];
__device__ __align__(16) uint4 gPh[2][3][16384];
__device__ __align__(16) uint4 gPp[512];
__device__ float gBias[6][HG_];
__device__ float g_h[3][B_][H_];
__device__ float g_c[3][B_][H_];
__device__ unsigned g_cnt = 0;
__device__ volatile unsigned g_gen = 0;
__device__ unsigned g_cnt4[4*32];
__device__ volatile unsigned g_gen4[4*32];

__device__ __forceinline__ float sigmoidf_(float x){ return 1.f/(1.f+expf(-x)); }
__device__ __forceinline__ void bsplit(float v, unsigned short& h, unsigned short& l){
    __nv_bfloat16 bh = __float2bfloat16(v);
    __nv_bfloat16 bl = __float2bfloat16(v - __bfloat162float(bh));
    h = __bfloat16_as_ushort(bh); l = __bfloat16_as_ushort(bl);
}
__device__ __forceinline__ unsigned packu(unsigned short e, unsigned short o){
    return (unsigned)e | ((unsigned)o << 16);
}
__device__ __forceinline__ void grid_barrier(){
    __syncthreads();
    if (threadIdx.x == 0){
        __threadfence();
        unsigned gen = g_gen;
        if (atomicAdd(&g_cnt,1u) == NCTA-1){ g_cnt = 0; __threadfence(); g_gen = gen+1; }
        else { while (g_gen == gen) {} }
        __threadfence();
    }
    __syncthreads();
}
// 64-CTA group barrier (4 independent bt-groups)
__device__ __forceinline__ void group_barrier(int grp){
    __syncthreads();
    if (threadIdx.x == 0){
        __threadfence();
        unsigned* cnt = &g_cnt4[grp*32];
        volatile unsigned* gen = &g_gen4[grp*32];
        unsigned gv = *gen;
        if (atomicAdd(cnt,1u) == 63){ *cnt = 0; __threadfence(); *gen = gv+1; }
        else { while (*gen == gv) {} }
        __threadfence();
    }
    __syncthreads();
}
__device__ __forceinline__ void mma_bf16(float* d, const uint4 a, unsigned b0, unsigned b1){
    asm volatile("mma.sync.aligned.m16n8k16.row.col.f32.bf16.bf16.f32 "
        "{%0,%1,%2,%3}, {%4,%5,%6,%7}, {%8,%9}, {%0,%1,%2,%3};"
        : "+f"(d[0]), "+f"(d[1]), "+f"(d[2]), "+f"(d[3])
        : "r"(a.x), "r"(a.y), "r"(a.z), "r"(a.w), "r"(b0), "r"(b1));
}

// fused layer-step: CTA tile 32b x 8j x 4 quadrants; 8 warps = 4 kg x 2 mw.
// Per-warp mainloop identical to the R7 winner (depth-1 reg prefetch).
__device__ __noinline__ void layer_step(
    float* sred, int tid,
    const uint4* __restrict__ pA1, int nk1,
    const uint4* __restrict__ pA2,
    const uint4* __restrict__ pW, const float* __restrict__ bias,
    int l, uint4* __restrict__ pHw, int j0, int bt)
{
    const int wid = tid>>5, lane = tid&31;
    const int kg = wid>>1, mw = wid&1;
    const int NK16 = nk1 + 32;
    const int mtile = bt*2 + mw;
    const int g = lane>>2, tig = lane&3;
    const int nb = j0>>3;

    const uint4* wp0 = pW + ((size_t)(0*64 + nb)*NK16 + kg)*32 + lane;
    const uint4* wp1 = pW + ((size_t)(1*64 + nb)*NK16 + kg)*32 + lane;
    const uint4* wp2 = pW + ((size_t)(2*64 + nb)*NK16 + kg)*32 + lane;
    const uint4* wp3 = pW + ((size_t)(3*64 + nb)*NK16 + kg)*32 + lane;

    float acc[4][4];
    #pragma unroll
    for (int q = 0; q < 4; q++){ acc[q][0]=acc[q][1]=acc[q][2]=acc[q][3]=0.f; }

    auto aptr = [&](int i) -> const uint4* {
        return (i < nk1) ? pA1 + ((size_t)(mtile*nk1 + i)*32 + lane)*2
                         : pA2 + ((size_t)(mtile*32 + (i-nk1))*32 + lane)*2;
    };

    uint4 ahi, alo, w0, w1, w2, w3;
    { const uint4* ap = aptr(kg); ahi = ap[0]; alo = ap[1];
      w0 = *wp0; w1 = *wp1; w2 = *wp2; w3 = *wp3; }

    for (int i = kg; i < NK16; i += 4){
        uint4 nahi, nalo, nw0, nw1, nw2, nw3;
        if (i + 4 < NK16){
            const uint4* ap = aptr(i+4);
            nahi = ap[0]; nalo = ap[1];
            nw0 = wp0[128]; nw1 = wp1[128]; nw2 = wp2[128]; nw3 = wp3[128];
        }
        mma_bf16(acc[0], ahi, w0.x, w0.y);
        mma_bf16(acc[1], ahi, w1.x, w1.y);
        mma_bf16(acc[2], ahi, w2.x, w2.y);
        mma_bf16(acc[3], ahi, w3.x, w3.y);
        mma_bf16(acc[0], ahi, w0.z, w0.w);
        mma_bf16(acc[1], ahi, w1.z, w1.w);
        mma_bf16(acc[2], ahi, w2.z, w2.w);
        mma_bf16(acc[3], ahi, w3.z, w3.w);
        mma_bf16(acc[0], alo, w0.x, w0.y);
        mma_bf16(acc[1], alo, w1.x, w1.y);
        mma_bf16(acc[2], alo, w2.x, w2.y);
        mma_bf16(acc[3], alo, w3.x, w3.y);
        wp0 += 128; wp1 += 128; wp2 += 128; wp3 += 128;
        ahi = nahi; alo = nalo; w0 = nw0; w1 = nw1; w2 = nw2; w3 = nw3;
    }

    __syncthreads();
    {   // partial D -> sred[kg][q*8+jl][b_l], stride 36
        float* rg = sred + kg*1152;
        #pragma unroll
        for (int q = 0; q < 4; q++){
            float* t0 = rg + (q*8 + 2*tig)*36 + mw*16;
            t0[g] = acc[q][0]; t0[g+8] = acc[q][2];
            t0[36+g] = acc[q][1]; t0[36+g+8] = acc[q][3];
        }
    }
    __syncthreads();

    {   // cell phase: 256 threads -> (b_l = tid>>3, j_l = tid&7)
        const int b_l = tid>>3, j_l = tid&7;
        float gate[4];
        #pragma unroll
        for (int q = 0; q < 4; q++){
            float s = 0.f;
            #pragma unroll
            for (int kk = 0; kk < 4; kk++) s += sred[kk*1152 + (q*8+j_l)*36 + b_l];
            gate[q] = s + bias[q*H_ + j0 + j_l];
        }
        const int b = bt*32 + b_l, j = j0 + j_l;
        float co = g_c[l][b][j];
        float cn = sigmoidf_(gate[1])*co + sigmoidf_(gate[0])*tanhf(gate[2]);
        g_c[l][b][j] = cn;
        float hv = sigmoidf_(gate[3])*tanhf(cn);
        g_h[l][b][j] = hv;
        unsigned short hs, ls; bsplit(hv, hs, ls);
        int mt = b>>4, rb = b&15, gg = rb&7, a01 = rb>>3;
        int k16 = j>>4, kr = j&15, tg = (kr>>1)&3, r24 = kr>>3, half = kr&1;
        int regidx = a01 + (r24<<1);
        unsigned short* dst = (unsigned short*)
            (pHw + ((size_t)(mt*32 + k16)*32 + (gg*4 + tg))*2);
        dst[regidx*2 + half] = hs;
        dst[8 + regidx*2 + half] = ls;
    }
}

__global__ __launch_bounds__(NTHR, 2) void lstm_persist(
    const float* __restrict__ x,
    const float* __restrict__ eWih0, const float* __restrict__ eWih,
    const float* __restrict__ eWhh,  const float* __restrict__ ebih,
    const float* __restrict__ ebhh,
    const float* __restrict__ dWih0, const float* __restrict__ dWih,
    const float* __restrict__ dWhh,  const float* __restrict__ dbih,
    const float* __restrict__ dbhh,
    const float* __restrict__ fcw,   const float* __restrict__ fcb,
    float* __restrict__ out)
{
    __shared__ float sred[4*1152];
    const int tid = threadIdx.x;
    const int bt = blockIdx.x >> 6;          // batch group 0..3
    const int cig = blockIdx.x & 63;          // CTA within group
    const int j0 = cig * 8;                   // 8-wide j slice
    const int grp = bt;
    const int gid = blockIdx.x*NTHR + tid;
    const size_t WS = (size_t)HG_*H_;

    // ---------------- init + packing ----------------
    for (int i = gid; i < 3*B_*H_; i += NTOT) (&g_c[0][0][0])[i] = 0.f;
    for (int i = gid; i < 2*3*16384; i += NTOT) (&gPh[0][0][0])[i] = make_uint4(0,0,0,0);
    {
        const float* bis[6] = {ebih, ebih+HG_, ebih+2*HG_, dbih, dbih+HG_, dbih+2*HG_};
        const float* bhs[6] = {ebhh, ebhh+HG_, ebhh+2*HG_, dbhh, dbhh+HG_, dbhh+2*HG_};
        for (int i = gid; i < 6*HG_; i += NTOT){
            int s = i >> 11, n = i & (HG_-1);
            gBias[s][n] = bis[s][n] + bhs[s][n];
        }
    }
    if (gid < 256){   // seed decoder input x[:, FIN-1, 0:FOUT]
        int mt = gid>>5, lane = gid&31, g = lane>>2, tig = lane&3;
        unsigned short hv[8], lv[8];
        #pragma unroll
        for (int ri = 0; ri < 4; ri++){
            int r24 = ri>>1, a01 = ri&1;
            #pragma unroll
            for (int half = 0; half < 2; half++){
                int k = r24*8 + 2*tig + half;
                int b = mt*16 + a01*8 + g;
                float v = (k < FOUT) ? x[(size_t)b*(FIN*T_) + (size_t)(FIN-1)*T_ + k] : 0.f;
                bsplit(v, hv[ri*2+half], lv[ri*2+half]);
            }
        }
        gPp[(size_t)(mt*32+lane)*2]   = make_uint4(packu(hv[0],hv[1]),packu(hv[2],hv[3]),packu(hv[4],hv[5]),packu(hv[6],hv[7]));
        gPp[(size_t)(mt*32+lane)*2+1] = make_uint4(packu(lv[0],lv[1]),packu(lv[2],lv[3]),packu(lv[4],lv[5]),packu(lv[6],lv[7]));
    }
    for (int idx = gid; idx < T_*8*4*32; idx += NTOT){   // pack x
        int lane = idx&31, k16 = (idx>>5)&3, mt = (idx>>7)&7, t = idx>>10;
        int g = lane>>2, tig = lane&3;
        int r0 = mt*16 + g, k0 = k16*16 + 2*tig;
        const float* xa = x + (size_t)r0*(FIN*T_) + t;
        const float* xb = x + (size_t)(r0+8)*(FIN*T_) + t;
        unsigned short h[8], l[8];
        bsplit(xa[(size_t)(k0  )*T_], h[0], l[0]); bsplit(xa[(size_t)(k0+1)*T_], h[1], l[1]);
        bsplit(xb[(size_t)(k0  )*T_], h[2], l[2]); bsplit(xb[(size_t)(k0+1)*T_], h[3], l[3]);
        bsplit(xa[(size_t)(k0+8)*T_], h[4], l[4]); bsplit(xa[(size_t)(k0+9)*T_], h[5], l[5]);
        bsplit(xb[(size_t)(k0+8)*T_], h[6], l[6]); bsplit(xb[(size_t)(k0+9)*T_], h[7], l[7]);
        gXp[(size_t)idx*2]   = make_uint4(packu(h[0],h[1]),packu(h[2],h[3]),packu(h[4],h[5]),packu(h[6],h[7]));
        gXp[(size_t)idx*2+1] = make_uint4(packu(l[0],l[1]),packu(l[2],l[3]),packu(l[4],l[5]),packu(l[6],l[7]));
    }
    {   // pack weights
        const float* W1s[6] = {eWih0, eWih, eWih+WS, dWih0, dWih, dWih+WS};
        const float* W2s[6] = {eWhh, eWhh+WS, eWhh+2*WS, dWhh, dWhh+WS, dWhh+2*WS};
        const int K1s[6] = {64,512,512,8,512,512};
        const int nk1s[6] = {4,32,32,1,32,32};
        for (int s = 0; s < 6; s++){
            const float* W1 = W1s[s]; const float* W2 = W2s[s];
            const int K1 = K1s[s], NK16 = nk1s[s]+32, nk1 = nk1s[s];
            for (int idx = gid; idx < 256*NK16*32; idx += NTOT){
                int lane = idx&31, k16 = (idx>>5)%NK16, ntile = (idx>>5)/NK16;
                int g = lane>>2, tig = lane&3;
                int n = ntile*8 + g, kb = k16*16 + 2*tig;
                float v00,v01,v10,v11;
                if (k16 < nk1){
                    v00 = (kb  <K1)? W1[(size_t)n*K1+kb]  :0.f;
                    v01 = (kb+1<K1)? W1[(size_t)n*K1+kb+1]:0.f;
                    v10 = (kb+8<K1)? W1[(size_t)n*K1+kb+8]:0.f;
                    v11 = (kb+9<K1)? W1[(size_t)n*K1+kb+9]:0.f;
                } else {
                    int k2 = kb - nk1*16;
                    v00 = W2[(size_t)n*H_+k2];   v01 = W2[(size_t)n*H_+k2+1];
                    v10 = W2[(size_t)n*H_+k2+8]; v11 = W2[(size_t)n*H_+k2+9];
                }
                unsigned short h00,l00,h01,l01,h10,l10,h11,l11;
                bsplit(v00,h00,l00); bsplit(v01,h01,l01);
                bsplit(v10,h10,l10); bsplit(v11,h11,l11);
                gWp[s][idx] = make_uint4(packu(h00,h01),packu(h10,h11),packu(l00,l01),packu(l10,l11));
            }
        }
    }
    grid_barrier();

    // -------- encoder: layer wavefront, 1 group barrier / super-step --------
    int rp0 = 0, rp1 = 0, rp2 = 0;
    for (int s = 0; s < T_ + 2; ++s){
        int r0 = rp0, r1 = rp1, r2 = rp2;
        if (s < T_){
            layer_step(sred, tid, gXp+(size_t)s*2048, 4, &gPh[r0][0][0],
                       gWp[0], gBias[0], 0, &gPh[r0^1][0][0], j0, bt);
            rp0 ^= 1;
        }
        if (s >= 1 && s < T_ + 1){
            layer_step(sred, tid, &gPh[r0][0][0], 32, &gPh[r1][1][0],
                       gWp[1], gBias[1], 1, &gPh[r1^1][1][0], j0, bt);
            rp1 ^= 1;
        }
        if (s >= 2){
            layer_step(sred, tid, &gPh[r1][1][0], 32, &gPh[r2][2][0],
                       gWp[2], gBias[2], 2, &gPh[r2^1][2][0], j0, bt);
            rp2 ^= 1;
        }
        group_barrier(grp);
    }

    // -------- decoder: serial 4-phase loop --------
    for (int d = 0; d < WOUT; ++d){
        layer_step(sred, tid, gPp, 1, &gPh[rp0][0][0],
                   gWp[3], gBias[3], 0, &gPh[rp0^1][0][0], j0, bt);
        rp0 ^= 1; group_barrier(grp);
        layer_step(sred, tid, &gPh[rp0][0][0], 32, &gPh[rp1][1][0],
                   gWp[4], gBias[4], 1, &gPh[rp1^1][1][0], j0, bt);
        rp1 ^= 1; group_barrier(grp);
        layer_step(sred, tid, &gPh[rp1][1][0], 32, &gPh[rp2][2][0],
                   gWp[5], gBias[5], 2, &gPh[rp2^1][2][0], j0, bt);
        rp2 ^= 1; group_barrier(grp);
        if (cig < 32){   // FC head: one CTA per batch row of this group
            int f = tid>>5, lnn = tid&31, b = bt*32 + cig;
            const float* hrow = &g_h[2][b][0];
            const float* wrow = fcw + f*H_;
            float ssum = 0.f;
            #pragma unroll 4
            for (int j = lnn; j < H_; j += 32) ssum += hrow[j]*wrow[j];
            #pragma unroll
            for (int o = 16; o; o >>= 1) ssum += __shfl_down_sync(0xffffffffu, ssum, o);
            if (lnn == 0){
                float v = ssum + fcb[f];
                out[(size_t)b*(FOUT*WOUT) + f*WOUT + d] = v;
                unsigned short hs, ls; bsplit(v, hs, ls);
                int mt = b>>4, gg = b&7, a01 = (b>>3)&1;
                int tg = (f>>1)&3, half = f&1;
                unsigned short* dst = (unsigned short*)
                    (gPp + ((size_t)mt*32 + (gg*4 + tg))*2);
                dst[a01*2 + half] = hs;
                dst[8 + a01*2 + half] = ls;
            }
        }
        group_barrier(grp);
    }
}

extern "C" void kernel_launch(void* const* d_in, const int* in_sizes, int n_in,
                              void* d_out, int out_size)
{
    lstm_persist<<<NCTA, NTHR>>>(
        (const float*)d_in[0], (const float*)d_in[1], (const float*)d_in[2],
        (const float*)d_in[3], (const float*)d_in[4], (const float*)d_in[5],
        (const float*)d_in[6], (const float*)d_in[7], (const float*)d_in[8],
        (const float*)d_in[9], (const float*)d_in[10], (const float*)d_in[11],
        (const float*)d_in[12], (float*)d_out);
}

// round 15
// speedup vs baseline: 1.7949x; 1.0445x over previous
#include <cuda_runtime.h>
#include <cuda_bf16.h>

#define B_ 128
#define H_ 512
#define HG_ 2048
#define T_ 512
#define FIN 64
#define FOUT 8
#define WOUT 64
#define NCTA 128
#define NTHR 512
#define NTOT (NCTA*NTHR)
#define SRED_BYTES (8*2304*4)   // 8 kg x 64 rows x 36 cols x 4B = 73728

// W: [(ntile*NK16+k16)*32+lane] = {b0h,b1h,b0l,b1l}
// A: [((mtile*nk+k16)*32+lane)*2 + {0hi,1lo}]
__device__ __align__(16) uint4 gWp[6][524288];
__device__ __align__(16) uint4 gXp[1048576];
__device__ __align__(16) uint4 gPh[2][3][16384];
__device__ __align__(16) uint4 gPp[512];
__device__ float gBias[6][HG_];
__device__ float g_h[3][B_][H_];
__device__ float g_c[3][B_][H_];
__device__ unsigned g_cnt = 0;
__device__ volatile unsigned g_gen = 0;
__device__ unsigned g_cnt4[4*32];
__device__ volatile unsigned g_gen4[4*32];

__device__ __forceinline__ float sigmoidf_(float x){ return 1.f/(1.f+expf(-x)); }
__device__ __forceinline__ void bsplit(float v, unsigned short& h, unsigned short& l){
    __nv_bfloat16 bh = __float2bfloat16(v);
    __nv_bfloat16 bl = __float2bfloat16(v - __bfloat162float(bh));
    h = __bfloat16_as_ushort(bh); l = __bfloat16_as_ushort(bl);
}
__device__ __forceinline__ unsigned packu(unsigned short e, unsigned short o){
    return (unsigned)e | ((unsigned)o << 16);
}
__device__ __forceinline__ void grid_barrier(){
    __syncthreads();
    if (threadIdx.x == 0){
        __threadfence();
        unsigned gen = g_gen;
        if (atomicAdd(&g_cnt,1u) == NCTA-1){ g_cnt = 0; __threadfence(); g_gen = gen+1; }
        else { while (g_gen == gen) {} }
        __threadfence();
    }
    __syncthreads();
}
__device__ __forceinline__ void group_barrier(int grp){
    __syncthreads();
    if (threadIdx.x == 0){
        __threadfence();
        unsigned* cnt = &g_cnt4[grp*32];
        volatile unsigned* gen = &g_gen4[grp*32];
        unsigned gv = *gen;
        if (atomicAdd(cnt,1u) == 31){ *cnt = 0; __threadfence(); *gen = gv+1; }
        else { while (*gen == gv) {} }
        __threadfence();
    }
    __syncthreads();
}
__device__ __forceinline__ void mma_bf16(float* d, const uint4 a, unsigned b0, unsigned b1){
    asm volatile("mma.sync.aligned.m16n8k16.row.col.f32.bf16.bf16.f32 "
        "{%0,%1,%2,%3}, {%4,%5,%6,%7}, {%8,%9}, {%0,%1,%2,%3};"
        : "+f"(d[0]), "+f"(d[1]), "+f"(d[2]), "+f"(d[3])
        : "r"(a.x), "r"(a.y), "r"(a.z), "r"(a.w), "r"(b0), "r"(b1));
}

// fused layer-step: CTA tile 32b x 16j x 4 quadrants.
// 16 warps = 8 kg x 2 jh; warp tile m32 x n8 (W read ONCE per CTA - no mw dup).
__device__ __noinline__ void layer_step(
    float* sred, int tid,
    const uint4* __restrict__ pA1, int nk1,
    const uint4* __restrict__ pA2,
    const uint4* __restrict__ pW, const float* __restrict__ bias,
    int l, uint4* __restrict__ pHw, int j0, int bt)
{
    const int wid = tid>>5, lane = tid&31;
    const int kg = wid>>1, jh = wid&1;
    const int NK16 = nk1 + 32;
    const int g = lane>>2, tig = lane&3;
    const int nb = (j0>>3) + jh;
    const int mt0 = bt*2, mt1 = bt*2 + 1;

    const uint4* wp0 = pW + ((size_t)(0*64 + nb)*NK16 + kg)*32 + lane;
    const uint4* wp1 = pW + ((size_t)(1*64 + nb)*NK16 + kg)*32 + lane;
    const uint4* wp2 = pW + ((size_t)(2*64 + nb)*NK16 + kg)*32 + lane;
    const uint4* wp3 = pW + ((size_t)(3*64 + nb)*NK16 + kg)*32 + lane;

    float acc[2][4][4];
    #pragma unroll
    for (int m = 0; m < 2; m++)
        #pragma unroll
        for (int q = 0; q < 4; q++)
            { acc[m][q][0]=acc[m][q][1]=acc[m][q][2]=acc[m][q][3]=0.f; }

    auto aptr = [&](int mtile, int i) -> const uint4* {
        return (i < nk1) ? pA1 + ((size_t)(mtile*nk1 + i)*32 + lane)*2
                         : pA2 + ((size_t)(mtile*32 + (i-nk1))*32 + lane)*2;
    };

    uint4 w0, w1, w2, w3, a0h, a0l, a1h, a1l;
    {
        const uint4* p0 = aptr(mt0, kg); a0h = p0[0]; a0l = p0[1];
        const uint4* p1 = aptr(mt1, kg); a1h = p1[0]; a1l = p1[1];
        w0 = *wp0; w1 = *wp1; w2 = *wp2; w3 = *wp3;
    }

    for (int i = kg; i < NK16; i += 8){
        uint4 nw0, nw1, nw2, nw3, n0h, n0l, n1h, n1l;
        if (i + 8 < NK16){
            const uint4* p0 = aptr(mt0, i+8); n0h = p0[0]; n0l = p0[1];
            const uint4* p1 = aptr(mt1, i+8); n1h = p1[0]; n1l = p1[1];
            nw0 = wp0[256]; nw1 = wp1[256]; nw2 = wp2[256]; nw3 = wp3[256];
        }
        // m32 tile: both mtiles share the same W fragments (dedup)
        mma_bf16(acc[0][0], a0h, w0.x, w0.y);
        mma_bf16(acc[1][0], a1h, w0.x, w0.y);
        mma_bf16(acc[0][1], a0h, w1.x, w1.y);
        mma_bf16(acc[1][1], a1h, w1.x, w1.y);
        mma_bf16(acc[0][2], a0h, w2.x, w2.y);
        mma_bf16(acc[1][2], a1h, w2.x, w2.y);
        mma_bf16(acc[0][3], a0h, w3.x, w3.y);
        mma_bf16(acc[1][3], a1h, w3.x, w3.y);
        mma_bf16(acc[0][0], a0h, w0.z, w0.w);
        mma_bf16(acc[1][0], a1h, w0.z, w0.w);
        mma_bf16(acc[0][1], a0h, w1.z, w1.w);
        mma_bf16(acc[1][1], a1h, w1.z, w1.w);
        mma_bf16(acc[0][2], a0h, w2.z, w2.w);
        mma_bf16(acc[1][2], a1h, w2.z, w2.w);
        mma_bf16(acc[0][3], a0h, w3.z, w3.w);
        mma_bf16(acc[1][3], a1h, w3.z, w3.w);
        mma_bf16(acc[0][0], a0l, w0.x, w0.y);
        mma_bf16(acc[1][0], a1l, w0.x, w0.y);
        mma_bf16(acc[0][1], a0l, w1.x, w1.y);
        mma_bf16(acc[1][1], a1l, w1.x, w1.y);
        mma_bf16(acc[0][2], a0l, w2.x, w2.y);
        mma_bf16(acc[1][2], a1l, w2.x, w2.y);
        mma_bf16(acc[0][3], a0l, w3.x, w3.y);
        mma_bf16(acc[1][3], a1l, w3.x, w3.y);
        wp0 += 256; wp1 += 256; wp2 += 256; wp3 += 256;
        w0 = nw0; w1 = nw1; w2 = nw2; w3 = nw3;
        a0h = n0h; a0l = n0l; a1h = n1h; a1l = n1l;
    }

    __syncthreads();
    {   // partial D -> sred[kg][q*16 + jh*8 + jfrag][mt*16 + b]
        float* rg = sred + kg*2304;
        #pragma unroll
        for (int m = 0; m < 2; m++)
            #pragma unroll
            for (int q = 0; q < 4; q++){
                float* t0 = rg + (q*16 + jh*8 + 2*tig)*36 + m*16;
                t0[g] = acc[m][q][0]; t0[g+8] = acc[m][q][2];
                t0[36+g] = acc[m][q][1]; t0[36+g+8] = acc[m][q][3];
            }
    }
    __syncthreads();

    {   // cell phase: thread -> (b_l = tid>>4, j_l = tid&15)
        const int b_l = tid>>4, j_l = tid&15;
        float gate[4];
        #pragma unroll
        for (int q = 0; q < 4; q++){
            float s = 0.f;
            #pragma unroll
            for (int kk = 0; kk < 8; kk++) s += sred[kk*2304 + (q*16+j_l)*36 + b_l];
            gate[q] = s + bias[q*H_ + j0 + j_l];
        }
        const int b = bt*32 + b_l, j = j0 + j_l;
        float co = g_c[l][b][j];
        float cn = sigmoidf_(gate[1])*co + sigmoidf_(gate[0])*tanhf(gate[2]);
        g_c[l][b][j] = cn;
        float hv = sigmoidf_(gate[3])*tanhf(cn);
        g_h[l][b][j] = hv;
        unsigned short hs, ls; bsplit(hv, hs, ls);
        int mt = b>>4, rb = b&15, gg = rb&7, a01 = rb>>3;
        int k16 = j>>4, kr = j&15, tg = (kr>>1)&3, r24 = kr>>3, half = kr&1;
        int regidx = a01 + (r24<<1);
        unsigned short* dst = (unsigned short*)
            (pHw + ((size_t)(mt*32 + k16)*32 + (gg*4 + tg))*2);
        dst[regidx*2 + half] = hs;
        dst[8 + regidx*2 + half] = ls;
    }
}

__global__ __launch_bounds__(NTHR, 1) void lstm_persist(
    const float* __restrict__ x,
    const float* __restrict__ eWih0, const float* __restrict__ eWih,
    const float* __restrict__ eWhh,  const float* __restrict__ ebih,
    const float* __restrict__ ebhh,
    const float* __restrict__ dWih0, const float* __restrict__ dWih,
    const float* __restrict__ dWhh,  const float* __restrict__ dbih,
    const float* __restrict__ dbhh,
    const float* __restrict__ fcw,   const float* __restrict__ fcb,
    float* __restrict__ out)
{
    extern __shared__ float sred[];
    const int tid = threadIdx.x;
    const int bt = blockIdx.x >> 5;
    const int j0 = (blockIdx.x & 31)*16;
    const int grp = bt;
    const int gid = blockIdx.x*NTHR + tid;
    const size_t WS = (size_t)HG_*H_;

    // ---------------- init + packing ----------------
    for (int i = gid; i < 3*B_*H_; i += NTOT) (&g_c[0][0][0])[i] = 0.f;
    for (int i = gid; i < 2*3*16384; i += NTOT) (&gPh[0][0][0])[i] = make_uint4(0,0,0,0);
    {
        const float* bis[6] = {ebih, ebih+HG_, ebih+2*HG_, dbih, dbih+HG_, dbih+2*HG_};
        const float* bhs[6] = {ebhh, ebhh+HG_, ebhh+2*HG_, dbhh, dbhh+HG_, dbhh+2*HG_};
        for (int i = gid; i < 6*HG_; i += NTOT){
            int s = i >> 11, n = i & (HG_-1);
            gBias[s][n] = bis[s][n] + bhs[s][n];
        }
    }
    if (gid < 256){   // seed decoder input x[:, FIN-1, 0:FOUT]
        int mt = gid>>5, lane = gid&31, g = lane>>2, tig = lane&3;
        unsigned short hv[8], lv[8];
        #pragma unroll
        for (int ri = 0; ri < 4; ri++){
            int r24 = ri>>1, a01 = ri&1;
            #pragma unroll
            for (int half = 0; half < 2; half++){
                int k = r24*8 + 2*tig + half;
                int b = mt*16 + a01*8 + g;
                float v = (k < FOUT) ? x[(size_t)b*(FIN*T_) + (size_t)(FIN-1)*T_ + k] : 0.f;
                bsplit(v, hv[ri*2+half], lv[ri*2+half]);
            }
        }
        gPp[(size_t)(mt*32+lane)*2]   = make_uint4(packu(hv[0],hv[1]),packu(hv[2],hv[3]),packu(hv[4],hv[5]),packu(hv[6],hv[7]));
        gPp[(size_t)(mt*32+lane)*2+1] = make_uint4(packu(lv[0],lv[1]),packu(lv[2],lv[3]),packu(lv[4],lv[5]),packu(lv[6],lv[7]));
    }
    for (int idx = gid; idx < T_*8*4*32; idx += NTOT){   // pack x
        int lane = idx&31, k16 = (idx>>5)&3, mt = (idx>>7)&7, t = idx>>10;
        int g = lane>>2, tig = lane&3;
        int r0 = mt*16 + g, k0 = k16*16 + 2*tig;
        const float* xa = x + (size_t)r0*(FIN*T_) + t;
        const float* xb = x + (size_t)(r0+8)*(FIN*T_) + t;
        unsigned short h[8], l[8];
        bsplit(xa[(size_t)(k0  )*T_], h[0], l[0]); bsplit(xa[(size_t)(k0+1)*T_], h[1], l[1]);
        bsplit(xb[(size_t)(k0  )*T_], h[2], l[2]); bsplit(xb[(size_t)(k0+1)*T_], h[3], l[3]);
        bsplit(xa[(size_t)(k0+8)*T_], h[4], l[4]); bsplit(xa[(size_t)(k0+9)*T_], h[5], l[5]);
        bsplit(xb[(size_t)(k0+8)*T_], h[6], l[6]); bsplit(xb[(size_t)(k0+9)*T_], h[7], l[7]);
        gXp[(size_t)idx*2]   = make_uint4(packu(h[0],h[1]),packu(h[2],h[3]),packu(h[4],h[5]),packu(h[6],h[7]));
        gXp[(size_t)idx*2+1] = make_uint4(packu(l[0],l[1]),packu(l[2],l[3]),packu(l[4],l[5]),packu(l[6],l[7]));
    }
    {   // pack weights
        const float* W1s[6] = {eWih0, eWih, eWih+WS, dWih0, dWih, dWih+WS};
        const float* W2s[6] = {eWhh, eWhh+WS, eWhh+2*WS, dWhh, dWhh+WS, dWhh+2*WS};
        const int K1s[6] = {64,512,512,8,512,512};
        const int nk1s[6] = {4,32,32,1,32,32};
        for (int s = 0; s < 6; s++){
            const float* W1 = W1s[s]; const float* W2 = W2s[s];
            const int K1 = K1s[s], NK16 = nk1s[s]+32, nk1 = nk1s[s];
            for (int idx = gid; idx < 256*NK16*32; idx += NTOT){
                int lane = idx&31, k16 = (idx>>5)%NK16, ntile = (idx>>5)/NK16;
                int g = lane>>2, tig = lane&3;
                int n = ntile*8 + g, kb = k16*16 + 2*tig;
                float v00,v01,v10,v11;
                if (k16 < nk1){
                    v00 = (kb  <K1)? W1[(size_t)n*K1+kb]  :0.f;
                    v01 = (kb+1<K1)? W1[(size_t)n*K1+kb+1]:0.f;
                    v10 = (kb+8<K1)? W1[(size_t)n*K1+kb+8]:0.f;
                    v11 = (kb+9<K1)? W1[(size_t)n*K1+kb+9]:0.f;
                } else {
                    int k2 = kb - nk1*16;
                    v00 = W2[(size_t)n*H_+k2];   v01 = W2[(size_t)n*H_+k2+1];
                    v10 = W2[(size_t)n*H_+k2+8]; v11 = W2[(size_t)n*H_+k2+9];
                }
                unsigned short h00,l00,h01,l01,h10,l10,h11,l11;
                bsplit(v00,h00,l00); bsplit(v01,h01,l01);
                bsplit(v10,h10,l10); bsplit(v11,h11,l11);
                gWp[s][idx] = make_uint4(packu(h00,h01),packu(h10,h11),packu(l00,l01),packu(l10,l11));
            }
        }
    }
    grid_barrier();

    // -------- encoder: layer wavefront, 1 group barrier / super-step --------
    int rp0 = 0, rp1 = 0, rp2 = 0;
    for (int s = 0; s < T_ + 2; ++s){
        int r0 = rp0, r1 = rp1, r2 = rp2;
        if (s < T_){
            layer_step(sred, tid, gXp+(size_t)s*2048, 4, &gPh[r0][0][0],
                       gWp[0], gBias[0], 0, &gPh[r0^1][0][0], j0, bt);
            rp0 ^= 1;
        }
        if (s >= 1 && s < T_ + 1){
            layer_step(sred, tid, &gPh[r0][0][0], 32, &gPh[r1][1][0],
                       gWp[1], gBias[1], 1, &gPh[r1^1][1][0], j0, bt);
            rp1 ^= 1;
        }
        if (s >= 2){
            layer_step(sred, tid, &gPh[r1][1][0], 32, &gPh[r2][2][0],
                       gWp[2], gBias[2], 2, &gPh[r2^1][2][0], j0, bt);
            rp2 ^= 1;
        }
        group_barrier(grp);
    }

    // -------- decoder: serial 4-phase loop --------
    for (int d = 0; d < WOUT; ++d){
        layer_step(sred, tid, gPp, 1, &gPh[rp0][0][0],
                   gWp[3], gBias[3], 0, &gPh[rp0^1][0][0], j0, bt);
        rp0 ^= 1; group_barrier(grp);
        layer_step(sred, tid, &gPh[rp0][0][0], 32, &gPh[rp1][1][0],
                   gWp[4], gBias[4], 1, &gPh[rp1^1][1][0], j0, bt);
        rp1 ^= 1; group_barrier(grp);
        layer_step(sred, tid, &gPh[rp1][1][0], 32, &gPh[rp2][2][0],
                   gWp[5], gBias[5], 2, &gPh[rp2^1][2][0], j0, bt);
        rp2 ^= 1; group_barrier(grp);
        if (tid < 256){   // FC head: CTA = batch row b
            int f = tid>>5, lnn = tid&31, b = blockIdx.x;
            const float* hrow = &g_h[2][b][0];
            const float* wrow = fcw + f*H_;
            float ssum = 0.f;
            #pragma unroll 4
            for (int j = lnn; j < H_; j += 32) ssum += hrow[j]*wrow[j];
            #pragma unroll
            for (int o = 16; o; o >>= 1) ssum += __shfl_down_sync(0xffffffffu, ssum, o);
            if (lnn == 0){
                float v = ssum + fcb[f];
                out[(size_t)b*(FOUT*WOUT) + f*WOUT + d] = v;
                unsigned short hs, ls; bsplit(v, hs, ls);
                int mt = b>>4, gg = b&7, a01 = (b>>3)&1;
                int tg = (f>>1)&3, half = f&1;
                unsigned short* dst = (unsigned short*)
                    (gPp + ((size_t)mt*32 + (gg*4 + tg))*2);
                dst[a01*2 + half] = hs;
                dst[8 + a01*2 + half] = ls;
            }
        }
        group_barrier(grp);
    }
}

extern "C" void kernel_launch(void* const* d_in, const int* in_sizes, int n_in,
                              void* d_out, int out_size)
{
    cudaFuncSetAttribute(lstm_persist,
                         cudaFuncAttributeMaxDynamicSharedMemorySize, SRED_BYTES);
    lstm_persist<<<NCTA, NTHR, SRED_BYTES>>>(
        (const float*)d_in[0], (const float*)d_in[1], (const float*)d_in[2],
        (const float*)d_in[3], (const float*)d_in[4], (const float*)d_in[5],
        (const float*)d_in[6], (const float*)d_in[7], (const float*)d_in[8],
        (const float*)d_in[9], (const float*)d_in[10], (const float*)d_in[11],
        (const float*)d_in[12], (float*)d_out);
}

// round 16
// speedup vs baseline: 2.2166x; 1.2350x over previous
#include <cuda_runtime.h>
#include <cuda_fp16.h>

#define B_ 128
#define H_ 512
#define HG_ 2048
#define T_ 512
#define FIN 64
#define FOUT 8
#define WOUT 64
#define NCTA 128
#define NTHR 512
#define NTOT (NCTA*NTHR)
#define SRED_BYTES (8*2304*4)   // 73728

// W: [(ntile*NK16+k16)*32+lane] = uint2 {b0, b1} fp16x2 (single precision term)
// A: [((mtile*nk+k16)*32+lane)*2 + {0hi,1lo}] = uint4 fragments (fp16 split)
__device__ __align__(16) uint2 gWp[6][524288];
__device__ __align__(16) uint4 gXp[1048576];
__device__ __align__(16) uint4 gPh[2][3][16384];
__device__ __align__(16) uint4 gPp[512];
__device__ float gBias[6][HG_];
__device__ float g_h[3][B_][H_];
__device__ float g_c[3][B_][H_];
__device__ unsigned g_cnt = 0;
__device__ volatile unsigned g_gen = 0;
__device__ unsigned g_cnt4[4*32];
__device__ volatile unsigned g_gen4[4*32];

__device__ __forceinline__ float sigmoidf_(float x){ return 1.f/(1.f+expf(-x)); }
// fp16 two-term split: v = h + l with |l| <= 2^-11 |v| (A side, exact products)
__device__ __forceinline__ void fsplit(float v, unsigned short& h, unsigned short& l){
    __half hh = __float2half_rn(v);
    __half ll = __float2half_rn(v - __half2float(hh));
    h = __half_as_ushort(hh); l = __half_as_ushort(ll);
}
__device__ __forceinline__ unsigned short f16s(float v){
    __half hh = __float2half_rn(v); return __half_as_ushort(hh);
}
__device__ __forceinline__ unsigned packu(unsigned short e, unsigned short o){
    return (unsigned)e | ((unsigned)o << 16);
}
__device__ __forceinline__ void grid_barrier(){
    __syncthreads();
    if (threadIdx.x == 0){
        __threadfence();
        unsigned gen = g_gen;
        if (atomicAdd(&g_cnt,1u) == NCTA-1){ g_cnt = 0; __threadfence(); g_gen = gen+1; }
        else { while (g_gen == gen) {} }
        __threadfence();
    }
    __syncthreads();
}
__device__ __forceinline__ void group_barrier(int grp){
    __syncthreads();
    if (threadIdx.x == 0){
        __threadfence();
        unsigned* cnt = &g_cnt4[grp*32];
        volatile unsigned* gen = &g_gen4[grp*32];
        unsigned gv = *gen;
        if (atomicAdd(cnt,1u) == 31){ *cnt = 0; __threadfence(); *gen = gv+1; }
        else { while (*gen == gv) {} }
        __threadfence();
    }
    __syncthreads();
}
__device__ __forceinline__ void mma_f16(float* d, const uint4 a, unsigned b0, unsigned b1){
    asm volatile("mma.sync.aligned.m16n8k16.row.col.f32.f16.f16.f32 "
        "{%0,%1,%2,%3}, {%4,%5,%6,%7}, {%8,%9}, {%0,%1,%2,%3};"
        : "+f"(d[0]), "+f"(d[1]), "+f"(d[2]), "+f"(d[3])
        : "r"(a.x), "r"(a.y), "r"(a.z), "r"(a.w), "r"(b0), "r"(b1));
}

// fused layer-step: CTA tile 32b x 16j x 4 quadrants.
// 16 warps = 8 kg x 2 jh; warp tile m32 x n8. W single-fp16 (2 MMA terms).
__device__ __noinline__ void layer_step(
    float* sred, int tid,
    const uint4* __restrict__ pA1, int nk1,
    const uint4* __restrict__ pA2,
    const uint2* __restrict__ pW, const float* __restrict__ bias,
    int l, uint4* __restrict__ pHw, int j0, int bt)
{
    const int wid = tid>>5, lane = tid&31;
    const int kg = wid>>1, jh = wid&1;
    const int NK16 = nk1 + 32;
    const int g = lane>>2, tig = lane&3;
    const int nb = (j0>>3) + jh;
    const int mt0 = bt*2, mt1 = bt*2 + 1;

    const uint2* wp0 = pW + ((size_t)(0*64 + nb)*NK16 + kg)*32 + lane;
    const uint2* wp1 = pW + ((size_t)(1*64 + nb)*NK16 + kg)*32 + lane;
    const uint2* wp2 = pW + ((size_t)(2*64 + nb)*NK16 + kg)*32 + lane;
    const uint2* wp3 = pW + ((size_t)(3*64 + nb)*NK16 + kg)*32 + lane;

    float acc[2][4][4];
    #pragma unroll
    for (int m = 0; m < 2; m++)
        #pragma unroll
        for (int q = 0; q < 4; q++)
            { acc[m][q][0]=acc[m][q][1]=acc[m][q][2]=acc[m][q][3]=0.f; }

    auto aptr = [&](int mtile, int i) -> const uint4* {
        return (i < nk1) ? pA1 + ((size_t)(mtile*nk1 + i)*32 + lane)*2
                         : pA2 + ((size_t)(mtile*32 + (i-nk1))*32 + lane)*2;
    };

    uint2 w0, w1, w2, w3;
    uint4 a0h, a0l, a1h, a1l;
    {
        const uint4* p0 = aptr(mt0, kg); a0h = p0[0]; a0l = p0[1];
        const uint4* p1 = aptr(mt1, kg); a1h = p1[0]; a1l = p1[1];
        w0 = *wp0; w1 = *wp1; w2 = *wp2; w3 = *wp3;
    }

    for (int i = kg; i < NK16; i += 8){
        uint2 nw0, nw1, nw2, nw3;
        uint4 n0h, n0l, n1h, n1l;
        if (i + 8 < NK16){
            const uint4* p0 = aptr(mt0, i+8); n0h = p0[0]; n0l = p0[1];
            const uint4* p1 = aptr(mt1, i+8); n1h = p1[0]; n1l = p1[1];
            nw0 = wp0[256]; nw1 = wp1[256]; nw2 = wp2[256]; nw3 = wp3[256];
        }
        // 2-term fp16: (ah + al) * W ; W exact in both products
        mma_f16(acc[0][0], a0h, w0.x, w0.y);
        mma_f16(acc[1][0], a1h, w0.x, w0.y);
        mma_f16(acc[0][1], a0h, w1.x, w1.y);
        mma_f16(acc[1][1], a1h, w1.x, w1.y);
        mma_f16(acc[0][2], a0h, w2.x, w2.y);
        mma_f16(acc[1][2], a1h, w2.x, w2.y);
        mma_f16(acc[0][3], a0h, w3.x, w3.y);
        mma_f16(acc[1][3], a1h, w3.x, w3.y);
        mma_f16(acc[0][0], a0l, w0.x, w0.y);
        mma_f16(acc[1][0], a1l, w0.x, w0.y);
        mma_f16(acc[0][1], a0l, w1.x, w1.y);
        mma_f16(acc[1][1], a1l, w1.x, w1.y);
        mma_f16(acc[0][2], a0l, w2.x, w2.y);
        mma_f16(acc[1][2], a1l, w2.x, w2.y);
        mma_f16(acc[0][3], a0l, w3.x, w3.y);
        mma_f16(acc[1][3], a1l, w3.x, w3.y);
        wp0 += 256; wp1 += 256; wp2 += 256; wp3 += 256;
        w0 = nw0; w1 = nw1; w2 = nw2; w3 = nw3;
        a0h = n0h; a0l = n0l; a1h = n1h; a1l = n1l;
    }

    __syncthreads();
    {
        float* rg = sred + kg*2304;
        #pragma unroll
        for (int m = 0; m < 2; m++)
            #pragma unroll
            for (int q = 0; q < 4; q++){
                float* t0 = rg + (q*16 + jh*8 + 2*tig)*36 + m*16;
                t0[g] = acc[m][q][0]; t0[g+8] = acc[m][q][2];
                t0[36+g] = acc[m][q][1]; t0[36+g+8] = acc[m][q][3];
            }
    }
    __syncthreads();

    {   // cell phase: thread -> (b_l = tid>>4, j_l = tid&15)
        const int b_l = tid>>4, j_l = tid&15;
        float gate[4];
        #pragma unroll
        for (int q = 0; q < 4; q++){
            float s = 0.f;
            #pragma unroll
            for (int kk = 0; kk < 8; kk++) s += sred[kk*2304 + (q*16+j_l)*36 + b_l];
            gate[q] = s + bias[q*H_ + j0 + j_l];
        }
        const int b = bt*32 + b_l, j = j0 + j_l;
        float co = g_c[l][b][j];
        float cn = sigmoidf_(gate[1])*co + sigmoidf_(gate[0])*tanhf(gate[2]);
        g_c[l][b][j] = cn;
        float hv = sigmoidf_(gate[3])*tanhf(cn);
        g_h[l][b][j] = hv;
        unsigned short hs, ls; fsplit(hv, hs, ls);
        int mt = b>>4, rb = b&15, gg = rb&7, a01 = rb>>3;
        int k16 = j>>4, kr = j&15, tg = (kr>>1)&3, r24 = kr>>3, half = kr&1;
        int regidx = a01 + (r24<<1);
        unsigned short* dst = (unsigned short*)
            (pHw + ((size_t)(mt*32 + k16)*32 + (gg*4 + tg))*2);
        dst[regidx*2 + half] = hs;
        dst[8 + regidx*2 + half] = ls;
    }
}

__global__ __launch_bounds__(NTHR, 1) void lstm_persist(
    const float* __restrict__ x,
    const float* __restrict__ eWih0, const float* __restrict__ eWih,
    const float* __restrict__ eWhh,  const float* __restrict__ ebih,
    const float* __restrict__ ebhh,
    const float* __restrict__ dWih0, const float* __restrict__ dWih,
    const float* __restrict__ dWhh,  const float* __restrict__ dbih,
    const float* __restrict__ dbhh,
    const float* __restrict__ fcw,   const float* __restrict__ fcb,
    float* __restrict__ out)
{
    extern __shared__ float sred[];
    const int tid = threadIdx.x;
    const int bt = blockIdx.x >> 5;
    const int j0 = (blockIdx.x & 31)*16;
    const int grp = bt;
    const int gid = blockIdx.x*NTHR + tid;
    const size_t WS = (size_t)HG_*H_;

    // ---------------- init + packing ----------------
    for (int i = gid; i < 3*B_*H_; i += NTOT) (&g_c[0][0][0])[i] = 0.f;
    for (int i = gid; i < 2*3*16384; i += NTOT) (&gPh[0][0][0])[i] = make_uint4(0,0,0,0);
    {
        const float* bis[6] = {ebih, ebih+HG_, ebih+2*HG_, dbih, dbih+HG_, dbih+2*HG_};
        const float* bhs[6] = {ebhh, ebhh+HG_, ebhh+2*HG_, dbhh, dbhh+HG_, dbhh+2*HG_};
        for (int i = gid; i < 6*HG_; i += NTOT){
            int s = i >> 11, n = i & (HG_-1);
            gBias[s][n] = bis[s][n] + bhs[s][n];
        }
    }
    if (gid < 256){   // seed decoder input x[:, FIN-1, 0:FOUT]
        int mt = gid>>5, lane = gid&31, g = lane>>2, tig = lane&3;
        unsigned short hv[8], lv[8];
        #pragma unroll
        for (int ri = 0; ri < 4; ri++){
            int r24 = ri>>1, a01 = ri&1;
            #pragma unroll
            for (int half = 0; half < 2; half++){
                int k = r24*8 + 2*tig + half;
                int b = mt*16 + a01*8 + g;
                float v = (k < FOUT) ? x[(size_t)b*(FIN*T_) + (size_t)(FIN-1)*T_ + k] : 0.f;
                fsplit(v, hv[ri*2+half], lv[ri*2+half]);
            }
        }
        gPp[(size_t)(mt*32+lane)*2]   = make_uint4(packu(hv[0],hv[1]),packu(hv[2],hv[3]),packu(hv[4],hv[5]),packu(hv[6],hv[7]));
        gPp[(size_t)(mt*32+lane)*2+1] = make_uint4(packu(lv[0],lv[1]),packu(lv[2],lv[3]),packu(lv[4],lv[5]),packu(lv[6],lv[7]));
    }
    for (int idx = gid; idx < T_*8*4*32; idx += NTOT){   // pack x (fp16 split)
        int lane = idx&31, k16 = (idx>>5)&3, mt = (idx>>7)&7, t = idx>>10;
        int g = lane>>2, tig = lane&3;
        int r0 = mt*16 + g, k0 = k16*16 + 2*tig;
        const float* xa = x + (size_t)r0*(FIN*T_) + t;
        const float* xb = x + (size_t)(r0+8)*(FIN*T_) + t;
        unsigned short h[8], l[8];
        fsplit(xa[(size_t)(k0  )*T_], h[0], l[0]); fsplit(xa[(size_t)(k0+1)*T_], h[1], l[1]);
        fsplit(xb[(size_t)(k0  )*T_], h[2], l[2]); fsplit(xb[(size_t)(k0+1)*T_], h[3], l[3]);
        fsplit(xa[(size_t)(k0+8)*T_], h[4], l[4]); fsplit(xa[(size_t)(k0+9)*T_], h[5], l[5]);
        fsplit(xb[(size_t)(k0+8)*T_], h[6], l[6]); fsplit(xb[(size_t)(k0+9)*T_], h[7], l[7]);
        gXp[(size_t)idx*2]   = make_uint4(packu(h[0],h[1]),packu(h[2],h[3]),packu(h[4],h[5]),packu(h[6],h[7]));
        gXp[(size_t)idx*2+1] = make_uint4(packu(l[0],l[1]),packu(l[2],l[3]),packu(l[4],l[5]),packu(l[6],l[7]));
    }
    {   // pack weights (single fp16)
        const float* W1s[6] = {eWih0, eWih, eWih+WS, dWih0, dWih, dWih+WS};
        const float* W2s[6] = {eWhh, eWhh+WS, eWhh+2*WS, dWhh, dWhh+WS, dWhh+2*WS};
        const int K1s[6] = {64,512,512,8,512,512};
        const int nk1s[6] = {4,32,32,1,32,32};
        for (int s = 0; s < 6; s++){
            const float* W1 = W1s[s]; const float* W2 = W2s[s];
            const int K1 = K1s[s], NK16 = nk1s[s]+32, nk1 = nk1s[s];
            for (int idx = gid; idx < 256*NK16*32; idx += NTOT){
                int lane = idx&31, k16 = (idx>>5)%NK16, ntile = (idx>>5)/NK16;
                int g = lane>>2, tig = lane&3;
                int n = ntile*8 + g, kb = k16*16 + 2*tig;
                float v00,v01,v10,v11;
                if (k16 < nk1){
                    v00 = (kb  <K1)? W1[(size_t)n*K1+kb]  :0.f;
                    v01 = (kb+1<K1)? W1[(size_t)n*K1+kb+1]:0.f;
                    v10 = (kb+8<K1)? W1[(size_t)n*K1+kb+8]:0.f;
                    v11 = (kb+9<K1)? W1[(size_t)n*K1+kb+9]:0.f;
                } else {
                    int k2 = kb - nk1*16;
                    v00 = W2[(size_t)n*H_+k2];   v01 = W2[(size_t)n*H_+k2+1];
                    v10 = W2[(size_t)n*H_+k2+8]; v11 = W2[(size_t)n*H_+k2+9];
                }
                uint2 o;
                o.x = packu(f16s(v00), f16s(v01));
                o.y = packu(f16s(v10), f16s(v11));
                gWp[s][idx] = o;
            }
        }
    }
    grid_barrier();

    // -------- encoder: layer wavefront, 1 group barrier / super-step --------
    int rp0 = 0, rp1 = 0, rp2 = 0;
    for (int s = 0; s < T_ + 2; ++s){
        int r0 = rp0, r1 = rp1, r2 = rp2;
        if (s < T_){
            layer_step(sred, tid, gXp+(size_t)s*2048, 4, &gPh[r0][0][0],
                       gWp[0], gBias[0], 0, &gPh[r0^1][0][0], j0, bt);
            rp0 ^= 1;
        }
        if (s >= 1 && s < T_ + 1){
            layer_step(sred, tid, &gPh[r0][0][0], 32, &gPh[r1][1][0],
                       gWp[1], gBias[1], 1, &gPh[r1^1][1][0], j0, bt);
            rp1 ^= 1;
        }
        if (s >= 2){
            layer_step(sred, tid, &gPh[r1][1][0], 32, &gPh[r2][2][0],
                       gWp[2], gBias[2], 2, &gPh[r2^1][2][0], j0, bt);
            rp2 ^= 1;
        }
        group_barrier(grp);
    }

    // -------- decoder: serial 4-phase loop --------
    for (int d = 0; d < WOUT; ++d){
        layer_step(sred, tid, gPp, 1, &gPh[rp0][0][0],
                   gWp[3], gBias[3], 0, &gPh[rp0^1][0][0], j0, bt);
        rp0 ^= 1; group_barrier(grp);
        layer_step(sred, tid, &gPh[rp0][0][0], 32, &gPh[rp1][1][0],
                   gWp[4], gBias[4], 1, &gPh[rp1^1][1][0], j0, bt);
        rp1 ^= 1; group_barrier(grp);
        layer_step(sred, tid, &gPh[rp1][1][0], 32, &gPh[rp2][2][0],
                   gWp[5], gBias[5], 2, &gPh[rp2^1][2][0], j0, bt);
        rp2 ^= 1; group_barrier(grp);
        if (tid < 256){   // FC head: CTA = batch row b
            int f = tid>>5, lnn = tid&31, b = blockIdx.x;
            const float* hrow = &g_h[2][b][0];
            const float* wrow = fcw + f*H_;
            float ssum = 0.f;
            #pragma unroll 4
            for (int j = lnn; j < H_; j += 32) ssum += hrow[j]*wrow[j];
            #pragma unroll
            for (int o = 16; o; o >>= 1) ssum += __shfl_down_sync(0xffffffffu, ssum, o);
            if (lnn == 0){
                float v = ssum + fcb[f];
                out[(size_t)b*(FOUT*WOUT) + f*WOUT + d] = v;
                unsigned short hs, ls; fsplit(v, hs, ls);
                int mt = b>>4, gg = b&7, a01 = (b>>3)&1;
                int tg = (f>>1)&3, half = f&1;
                unsigned short* dst = (unsigned short*)
                    (gPp + ((size_t)mt*32 + (gg*4 + tg))*2);
                dst[a01*2 + half] = hs;
                dst[8 + a01*2 + half] = ls;
            }
        }
        group_barrier(grp);
    }
}

extern "C" void kernel_launch(void* const* d_in, const int* in_sizes, int n_in,
                              void* d_out, int out_size)
{
    cudaFuncSetAttribute(lstm_persist,
                         cudaFuncAttributeMaxDynamicSharedMemorySize, SRED_BYTES);
    lstm_persist<<<NCTA, NTHR, SRED_BYTES>>>(
        (const float*)d_in[0], (const float*)d_in[1], (const float*)d_in[2],
        (const float*)d_in[3], (const float*)d_in[4], (const float*)d_in[5],
        (const float*)d_in[6], (const float*)d_in[7], (const float*)d_in[8],
        (const float*)d_in[9], (const float*)d_in[10], (const float*)d_in[11],
        (const float*)d_in[12], (float*)d_out);
}

// round 17
// speedup vs baseline: 2.5063x; 1.1307x over previous
#include <cuda_runtime.h>
#include <cuda_fp16.h>

#define B_ 128
#define H_ 512
#define HG_ 2048
#define T_ 512
#define FIN 64
#define FOUT 8
#define WOUT 64
#define NCTA 128
#define NTHR 512
#define NTOT (NCTA*NTHR)
#define SRED_BYTES (8*2304*4)   // 73728

// W: [(ntile*NK16+k16)*32+lane] = uint2 {b0, b1} fp16x2
// A: [(mtile*nk+k16)*32+lane] = uint4 fragment, single fp16
__device__ __align__(16) uint2 gWp[6][524288];
__device__ __align__(16) uint4 gXp[524288];
__device__ __align__(16) uint4 gPh[2][3][8192];
__device__ __align__(16) uint4 gPp[256];
__device__ float gBias[6][HG_];
__device__ float g_h[3][B_][H_];
__device__ float g_c[3][B_][H_];
__device__ unsigned g_cnt = 0;
__device__ volatile unsigned g_gen = 0;
__device__ unsigned g_cnt4[4*32];
__device__ volatile unsigned g_gen4[4*32];

__device__ __forceinline__ float sigmoidf_(float x){ return 1.f/(1.f+expf(-x)); }
__device__ __forceinline__ unsigned short f16s(float v){
    __half hh = __float2half_rn(v); return __half_as_ushort(hh);
}
__device__ __forceinline__ unsigned packu(unsigned short e, unsigned short o){
    return (unsigned)e | ((unsigned)o << 16);
}
__device__ __forceinline__ void grid_barrier(){
    __syncthreads();
    if (threadIdx.x == 0){
        __threadfence();
        unsigned gen = g_gen;
        if (atomicAdd(&g_cnt,1u) == NCTA-1){ g_cnt = 0; __threadfence(); g_gen = gen+1; }
        else { while (g_gen == gen) {} }
        __threadfence();
    }
    __syncthreads();
}
__device__ __forceinline__ void group_barrier(int grp){
    __syncthreads();
    if (threadIdx.x == 0){
        __threadfence();
        unsigned* cnt = &g_cnt4[grp*32];
        volatile unsigned* gen = &g_gen4[grp*32];
        unsigned gv = *gen;
        if (atomicAdd(cnt,1u) == 31){ *cnt = 0; __threadfence(); *gen = gv+1; }
        else { while (*gen == gv) {} }
        __threadfence();
    }
    __syncthreads();
}
__device__ __forceinline__ void mma_f16(float* d, const uint4 a, unsigned b0, unsigned b1){
    asm volatile("mma.sync.aligned.m16n8k16.row.col.f32.f16.f16.f32 "
        "{%0,%1,%2,%3}, {%4,%5,%6,%7}, {%8,%9}, {%0,%1,%2,%3};"
        : "+f"(d[0]), "+f"(d[1]), "+f"(d[2]), "+f"(d[3])
        : "r"(a.x), "r"(a.y), "r"(a.z), "r"(a.w), "r"(b0), "r"(b1));
}

// fused layer-step: CTA tile 32b x 16j x 4 quadrants.
// 16 warps = 8 kg x 2 jh; warp tile m32 x n8; single-fp16 A and W (8 MMA/k16).
__device__ __noinline__ void layer_step(
    float* sred, int tid,
    const uint4* __restrict__ pA1, int nk1,
    const uint4* __restrict__ pA2,
    const uint2* __restrict__ pW, const float* __restrict__ bias,
    int l, uint4* __restrict__ pHw, int j0, int bt)
{
    const int wid = tid>>5, lane = tid&31;
    const int kg = wid>>1, jh = wid&1;
    const int NK16 = nk1 + 32;
    const int g = lane>>2, tig = lane&3;
    const int nb = (j0>>3) + jh;
    const int mt0 = bt*2, mt1 = bt*2 + 1;

    const uint2* wp0 = pW + ((size_t)(0*64 + nb)*NK16 + kg)*32 + lane;
    const uint2* wp1 = pW + ((size_t)(1*64 + nb)*NK16 + kg)*32 + lane;
    const uint2* wp2 = pW + ((size_t)(2*64 + nb)*NK16 + kg)*32 + lane;
    const uint2* wp3 = pW + ((size_t)(3*64 + nb)*NK16 + kg)*32 + lane;

    float acc[2][4][4];
    #pragma unroll
    for (int m = 0; m < 2; m++)
        #pragma unroll
        for (int q = 0; q < 4; q++)
            { acc[m][q][0]=acc[m][q][1]=acc[m][q][2]=acc[m][q][3]=0.f; }

    auto aptr = [&](int mtile, int i) -> const uint4* {
        return (i < nk1) ? pA1 + (size_t)(mtile*nk1 + i)*32 + lane
                         : pA2 + (size_t)(mtile*32 + (i-nk1))*32 + lane;
    };

    uint2 w0, w1, w2, w3;
    uint4 a0, a1;
    {
        a0 = *aptr(mt0, kg); a1 = *aptr(mt1, kg);
        w0 = *wp0; w1 = *wp1; w2 = *wp2; w3 = *wp3;
    }

    for (int i = kg; i < NK16; i += 8){
        uint2 nw0, nw1, nw2, nw3;
        uint4 n0, n1;
        if (i + 8 < NK16){
            n0 = *aptr(mt0, i+8); n1 = *aptr(mt1, i+8);
            nw0 = wp0[256]; nw1 = wp1[256]; nw2 = wp2[256]; nw3 = wp3[256];
        }
        mma_f16(acc[0][0], a0, w0.x, w0.y);
        mma_f16(acc[1][0], a1, w0.x, w0.y);
        mma_f16(acc[0][1], a0, w1.x, w1.y);
        mma_f16(acc[1][1], a1, w1.x, w1.y);
        mma_f16(acc[0][2], a0, w2.x, w2.y);
        mma_f16(acc[1][2], a1, w2.x, w2.y);
        mma_f16(acc[0][3], a0, w3.x, w3.y);
        mma_f16(acc[1][3], a1, w3.x, w3.y);
        wp0 += 256; wp1 += 256; wp2 += 256; wp3 += 256;
        w0 = nw0; w1 = nw1; w2 = nw2; w3 = nw3;
        a0 = n0; a1 = n1;
    }

    __syncthreads();
    {
        float* rg = sred + kg*2304;
        #pragma unroll
        for (int m = 0; m < 2; m++)
            #pragma unroll
            for (int q = 0; q < 4; q++){
                float* t0 = rg + (q*16 + jh*8 + 2*tig)*36 + m*16;
                t0[g] = acc[m][q][0]; t0[g+8] = acc[m][q][2];
                t0[36+g] = acc[m][q][1]; t0[36+g+8] = acc[m][q][3];
            }
    }
    __syncthreads();

    {   // cell phase: thread -> (b_l = tid>>4, j_l = tid&15)
        const int b_l = tid>>4, j_l = tid&15;
        float gate[4];
        #pragma unroll
        for (int q = 0; q < 4; q++){
            float s = 0.f;
            #pragma unroll
            for (int kk = 0; kk < 8; kk++) s += sred[kk*2304 + (q*16+j_l)*36 + b_l];
            gate[q] = s + bias[q*H_ + j0 + j_l];
        }
        const int b = bt*32 + b_l, j = j0 + j_l;
        float co = g_c[l][b][j];
        float cn = sigmoidf_(gate[1])*co + sigmoidf_(gate[0])*tanhf(gate[2]);
        g_c[l][b][j] = cn;
        float hv = sigmoidf_(gate[3])*tanhf(cn);
        g_h[l][b][j] = hv;
        unsigned short hs = f16s(hv);
        int mt = b>>4, rb = b&15, gg = rb&7, a01 = rb>>3;
        int k16 = j>>4, kr = j&15, tg = (kr>>1)&3, r24 = kr>>3, half = kr&1;
        int regidx = a01 + (r24<<1);
        unsigned short* dst = (unsigned short*)
            (pHw + (size_t)(mt*32 + k16)*32 + (gg*4 + tg));
        dst[regidx*2 + half] = hs;
    }
}

__global__ __launch_bounds__(NTHR, 1) void lstm_persist(
    const float* __restrict__ x,
    const float* __restrict__ eWih0, const float* __restrict__ eWih,
    const float* __restrict__ eWhh,  const float* __restrict__ ebih,
    const float* __restrict__ ebhh,
    const float* __restrict__ dWih0, const float* __restrict__ dWih,
    const float* __restrict__ dWhh,  const float* __restrict__ dbih,
    const float* __restrict__ dbhh,
    const float* __restrict__ fcw,   const float* __restrict__ fcb,
    float* __restrict__ out)
{
    extern __shared__ float sred[];
    const int tid = threadIdx.x;
    const int bt = blockIdx.x >> 5;
    const int j0 = (blockIdx.x & 31)*16;
    const int grp = bt;
    const int gid = blockIdx.x*NTHR + tid;
    const size_t WS = (size_t)HG_*H_;

    // ---------------- init + packing ----------------
    for (int i = gid; i < 3*B_*H_; i += NTOT) (&g_c[0][0][0])[i] = 0.f;
    for (int i = gid; i < 2*3*8192; i += NTOT) (&gPh[0][0][0])[i] = make_uint4(0,0,0,0);
    {
        const float* bis[6] = {ebih, ebih+HG_, ebih+2*HG_, dbih, dbih+HG_, dbih+2*HG_};
        const float* bhs[6] = {ebhh, ebhh+HG_, ebhh+2*HG_, dbhh, dbhh+HG_, dbhh+2*HG_};
        for (int i = gid; i < 6*HG_; i += NTOT){
            int s = i >> 11, n = i & (HG_-1);
            gBias[s][n] = bis[s][n] + bhs[s][n];
        }
    }
    if (gid < 256){   // seed decoder input x[:, FIN-1, 0:FOUT]
        int mt = gid>>5, lane = gid&31, g = lane>>2, tig = lane&3;
        unsigned short hv[8];
        #pragma unroll
        for (int ri = 0; ri < 4; ri++){
            int r24 = ri>>1, a01 = ri&1;
            #pragma unroll
            for (int half = 0; half < 2; half++){
                int k = r24*8 + 2*tig + half;
                int b = mt*16 + a01*8 + g;
                float v = (k < FOUT) ? x[(size_t)b*(FIN*T_) + (size_t)(FIN-1)*T_ + k] : 0.f;
                hv[ri*2+half] = f16s(v);
            }
        }
        gPp[mt*32+lane] = make_uint4(packu(hv[0],hv[1]),packu(hv[2],hv[3]),
                                     packu(hv[4],hv[5]),packu(hv[6],hv[7]));
    }
    for (int idx = gid; idx < T_*8*4*32; idx += NTOT){   // pack x (single fp16)
        int lane = idx&31, k16 = (idx>>5)&3, mt = (idx>>7)&7, t = idx>>10;
        int g = lane>>2, tig = lane&3;
        int r0 = mt*16 + g, k0 = k16*16 + 2*tig;
        const float* xa = x + (size_t)r0*(FIN*T_) + t;
        const float* xb = x + (size_t)(r0+8)*(FIN*T_) + t;
        unsigned short h[8];
        h[0] = f16s(xa[(size_t)(k0  )*T_]); h[1] = f16s(xa[(size_t)(k0+1)*T_]);
        h[2] = f16s(xb[(size_t)(k0  )*T_]); h[3] = f16s(xb[(size_t)(k0+1)*T_]);
        h[4] = f16s(xa[(size_t)(k0+8)*T_]); h[5] = f16s(xa[(size_t)(k0+9)*T_]);
        h[6] = f16s(xb[(size_t)(k0+8)*T_]); h[7] = f16s(xb[(size_t)(k0+9)*T_]);
        gXp[idx] = make_uint4(packu(h[0],h[1]),packu(h[2],h[3]),
                              packu(h[4],h[5]),packu(h[6],h[7]));
    }
    {   // pack weights (single fp16)
        const float* W1s[6] = {eWih0, eWih, eWih+WS, dWih0, dWih, dWih+WS};
        const float* W2s[6] = {eWhh, eWhh+WS, eWhh+2*WS, dWhh, dWhh+WS, dWhh+2*WS};
        const int K1s[6] = {64,512,512,8,512,512};
        const int nk1s[6] = {4,32,32,1,32,32};
        for (int s = 0; s < 6; s++){
            const float* W1 = W1s[s]; const float* W2 = W2s[s];
            const int K1 = K1s[s], NK16 = nk1s[s]+32, nk1 = nk1s[s];
            for (int idx = gid; idx < 256*NK16*32; idx += NTOT){
                int lane = idx&31, k16 = (idx>>5)%NK16, ntile = (idx>>5)/NK16;
                int g = lane>>2, tig = lane&3;
                int n = ntile*8 + g, kb = k16*16 + 2*tig;
                float v00,v01,v10,v11;
                if (k16 < nk1){
                    v00 = (kb  <K1)? W1[(size_t)n*K1+kb]  :0.f;
                    v01 = (kb+1<K1)? W1[(size_t)n*K1+kb+1]:0.f;
                    v10 = (kb+8<K1)? W1[(size_t)n*K1+kb+8]:0.f;
                    v11 = (kb+9<K1)? W1[(size_t)n*K1+kb+9]:0.f;
                } else {
                    int k2 = kb - nk1*16;
                    v00 = W2[(size_t)n*H_+k2];   v01 = W2[(size_t)n*H_+k2+1];
                    v10 = W2[(size_t)n*H_+k2+8]; v11 = W2[(size_t)n*H_+k2+9];
                }
                uint2 o;
                o.x = packu(f16s(v00), f16s(v01));
                o.y = packu(f16s(v10), f16s(v11));
                gWp[s][idx] = o;
            }
        }
    }
    grid_barrier();

    // -------- encoder: layer wavefront, 1 group barrier / super-step --------
    int rp0 = 0, rp1 = 0, rp2 = 0;
    for (int s = 0; s < T_ + 2; ++s){
        int r0 = rp0, r1 = rp1, r2 = rp2;
        if (s < T_){
            layer_step(sred, tid, gXp+(size_t)s*1024, 4, &gPh[r0][0][0],
                       gWp[0], gBias[0], 0, &gPh[r0^1][0][0], j0, bt);
            rp0 ^= 1;
        }
        if (s >= 1 && s < T_ + 1){
            layer_step(sred, tid, &gPh[r0][0][0], 32, &gPh[r1][1][0],
                       gWp[1], gBias[1], 1, &gPh[r1^1][1][0], j0, bt);
            rp1 ^= 1;
        }
        if (s >= 2){
            layer_step(sred, tid, &gPh[r1][1][0], 32, &gPh[r2][2][0],
                       gWp[2], gBias[2], 2, &gPh[r2^1][2][0], j0, bt);
            rp2 ^= 1;
        }
        group_barrier(grp);
    }

    // -------- decoder: serial 4-phase loop --------
    for (int d = 0; d < WOUT; ++d){
        layer_step(sred, tid, gPp, 1, &gPh[rp0][0][0],
                   gWp[3], gBias[3], 0, &gPh[rp0^1][0][0], j0, bt);
        rp0 ^= 1; group_barrier(grp);
        layer_step(sred, tid, &gPh[rp0][0][0], 32, &gPh[rp1][1][0],
                   gWp[4], gBias[4], 1, &gPh[rp1^1][1][0], j0, bt);
        rp1 ^= 1; group_barrier(grp);
        layer_step(sred, tid, &gPh[rp1][1][0], 32, &gPh[rp2][2][0],
                   gWp[5], gBias[5], 2, &gPh[rp2^1][2][0], j0, bt);
        rp2 ^= 1; group_barrier(grp);
        if (tid < 256){   // FC head: CTA = batch row b
            int f = tid>>5, lnn = tid&31, b = blockIdx.x;
            const float* hrow = &g_h[2][b][0];
            const float* wrow = fcw + f*H_;
            float ssum = 0.f;
            #pragma unroll 4
            for (int j = lnn; j < H_; j += 32) ssum += hrow[j]*wrow[j];
            #pragma unroll
            for (int o = 16; o; o >>= 1) ssum += __shfl_down_sync(0xffffffffu, ssum, o);
            if (lnn == 0){
                float v = ssum + fcb[f];
                out[(size_t)b*(FOUT*WOUT) + f*WOUT + d] = v;
                unsigned short hs = f16s(v);
                int mt = b>>4, gg = b&7, a01 = (b>>3)&1;
                int tg = (f>>1)&3, half = f&1;
                unsigned short* dst = (unsigned short*)
                    (gPp + (size_t)mt*32 + (gg*4 + tg));
                dst[a01*2 + half] = hs;
            }
        }
        group_barrier(grp);
    }
}

extern "C" void kernel_launch(void* const* d_in, const int* in_sizes, int n_in,
                              void* d_out, int out_size)
{
    cudaFuncSetAttribute(lstm_persist,
                         cudaFuncAttributeMaxDynamicSharedMemorySize, SRED_BYTES);
    lstm_persist<<<NCTA, NTHR, SRED_BYTES>>>(
        (const float*)d_in[0], (const float*)d_in[1], (const float*)d_in[2],
        (const float*)d_in[3], (const float*)d_in[4], (const float*)d_in[5],
        (const float*)d_in[6], (const float*)d_in[7], (const float*)d_in[8],
        (const float*)d_in[9], (const float*)d_in[10], (const float*)d_in[11],
        (const float*)d_in[12], (float*)d_out);
}